// round 10
// baseline (speedup 1.0000x reference)
#include <cuda_runtime.h>
#include <cuda_fp16.h>
#include <math.h>
#include <stdint.h>

#define NTOK 4096
#define DM   256
#define HD   64
#define KSTR 72   // fp16 smem stride (halves): 64 + 8 pad
#define GSTR 72

// ---------------- scratch ----------------------------------------------------
__device__ __half g_qh[NTOK * DM], g_kh[NTOK * DM], g_vh[NTOK * DM];
__device__ __half g_WQ[DM * DM], g_WK[DM * DM], g_WV[DM * DM], g_WO[DM * DM];
__device__ __half g_Qh[NTOK * DM];   // projected Q (scaled by 0.125*log2e)
__device__ __half g_Kh[NTOK * DM];
__device__ __half g_Vh[NTOK * DM];
__device__ __half g_Oh[NTOK * DM];
__device__ float  g_cos[NTOK * 32];
__device__ float  g_sin[NTOK * 32];

// ---------------- helpers ----------------------------------------------------
__device__ __forceinline__ uint32_t smem_u32(const void* p) {
    uint32_t a;
    asm("{ .reg .u64 t; cvta.to.shared.u64 t, %1; cvt.u32.u64 %0, t; }" : "=r"(a) : "l"(p));
    return a;
}
__device__ __forceinline__ void cp16(uint32_t dst, const void* src) {
    asm volatile("cp.async.ca.shared.global [%0], [%1], 16;" :: "r"(dst), "l"(src));
}
#define CP_COMMIT() asm volatile("cp.async.commit_group;" ::: "memory")
#define CP_WAIT(n)  asm volatile("cp.async.wait_group %0;" :: "n"(n) : "memory")

__device__ __forceinline__ void ldsm4(uint32_t a, uint32_t& r0, uint32_t& r1,
                                      uint32_t& r2, uint32_t& r3) {
    asm volatile("ldmatrix.sync.aligned.m8n8.x4.shared.b16 {%0,%1,%2,%3}, [%4];"
                 : "=r"(r0), "=r"(r1), "=r"(r2), "=r"(r3) : "r"(a));
}
__device__ __forceinline__ void ldsm4t(uint32_t a, uint32_t& r0, uint32_t& r1,
                                       uint32_t& r2, uint32_t& r3) {
    asm volatile("ldmatrix.sync.aligned.m8n8.x4.trans.shared.b16 {%0,%1,%2,%3}, [%4];"
                 : "=r"(r0), "=r"(r1), "=r"(r2), "=r"(r3) : "r"(a));
}
__device__ __forceinline__ void mma16816(float* c, uint32_t a0, uint32_t a1,
                                         uint32_t a2, uint32_t a3,
                                         uint32_t b0, uint32_t b1) {
    asm volatile(
        "mma.sync.aligned.m16n8k16.row.col.f32.f16.f16.f32 "
        "{%0,%1,%2,%3},{%4,%5,%6,%7},{%8,%9},{%0,%1,%2,%3};"
        : "+f"(c[0]), "+f"(c[1]), "+f"(c[2]), "+f"(c[3])
        : "r"(a0), "r"(a1), "r"(a2), "r"(a3), "r"(b0), "r"(b1));
}
__device__ __forceinline__ uint32_t pack2(float lo, float hi) {
    __half2 h = __floats2half2_rn(lo, hi);
    return *(uint32_t*)&h;
}

// ---------------- prep: cvt fp32->fp16 (inputs+weights) + rope table ---------
__global__ void prep_kernel(const float* q, const float* k, const float* v,
                            const float* wq, const float* wk,
                            const float* wv, const float* wo) {
    const int NM4 = NTOK * DM / 4;       // 262144
    const int W4  = DM * DM / 4;         // 16384
    const int CVT = 3 * NM4 + 4 * W4;    // 851968
    int i = blockIdx.x * blockDim.x + threadIdx.x;
    if (i < CVT) {
        const float* src;
        __half* dst;
        int off;
        if (i < 3 * NM4) {
            int t = i / NM4; off = i - t * NM4;
            src = (t == 0) ? q : (t == 1) ? k : v;
            dst = (t == 0) ? g_qh : (t == 1) ? g_kh : g_vh;
        } else {
            int j = i - 3 * NM4;
            int t = j / W4; off = j - t * W4;
            src = (t == 0) ? wq : (t == 1) ? wk : (t == 2) ? wv : wo;
            dst = (t == 0) ? g_WQ : (t == 1) ? g_WK : (t == 2) ? g_WV : g_WO;
        }
        float4 f = ((const float4*)src)[off];
        uint2 h;
        h.x = pack2(f.x, f.y);
        h.y = pack2(f.z, f.w);
        ((uint2*)dst)[off] = h;
    } else {
        int idx = i - CVT;
        if (idx >= NTOK * 32) return;
        int n = idx >> 5;
        int j = idx & 31;
        float pos = (j < 16) ? (float)(n & 63) : (float)(n >> 6);
        int jj = j & 15;
        float f = expf(-(float)jj * (9.210340371976184f / 16.0f));
        float s, c;
        sincosf(pos * f, &s, &c);
        g_cos[idx] = c;
        g_sin[idx] = s;
    }
}

// ---------------- fp16 tensor GEMM body (shared by QKV and out proj) ---------
#define GEMM_SMEM 57600
__device__ __forceinline__ void gemm16_body(
    const __half* __restrict__ A, const __half* __restrict__ W,
    const float* __restrict__ bias, float* __restrict__ Cf,
    __half* __restrict__ Ch, int applyRope, float outScale) {
    extern __shared__ __align__(16) char gsm[];
    const uint32_t base = smem_u32(gsm);
    const int tid = threadIdx.x, wid = tid >> 5, L = tid & 31;
    const int bm = blockIdx.x * 128, bn = blockIdx.y * 64;

    const uint32_t aBuf[2] = {base, base + 18432};
    const uint32_t wBuf[2] = {base + 36864, base + 47232};

    auto loadChunk = [&](int k0, int b) {
        #pragma unroll
        for (int t = 0; t < 4; t++) {
            int it = tid + t * 256;
            int row = it >> 3, ch = it & 7;
            cp16(aBuf[b] + (row * GSTR + ch * 8) * 2, &A[(bm + row) * DM + k0 + ch * 8]);
        }
        #pragma unroll
        for (int t = 0; t < 2; t++) {
            int it = tid + t * 256;
            int row = it >> 3, ch = it & 7;
            cp16(wBuf[b] + (row * GSTR + ch * 8) * 2, &W[(k0 + row) * DM + bn + ch * 8]);
        }
        CP_COMMIT();
    };

    loadChunk(0, 0);

    const int brow = ((L >> 3) & 1) * 8 + (L & 7);
    const int bcol = (L >> 4) * 8;
    float acc[8][4] = {};

    #pragma unroll
    for (int kk = 0; kk < 4; kk++) {
        CP_WAIT(0);
        __syncthreads();
        if (kk < 3) loadChunk((kk + 1) * 64, (kk + 1) & 1);
        const uint32_t aA = aBuf[kk & 1];
        const uint32_t aW = wBuf[kk & 1];
        const uint32_t qaddr = aA + ((wid * 16 + (L & 15)) * GSTR + (L >> 4) * 8) * 2;
        #pragma unroll
        for (int kc4 = 0; kc4 < 4; kc4++) {
            const int kc = kc4 * 16;
            uint32_t a0, a1, a2, a3;
            ldsm4(qaddr + kc * 2, a0, a1, a2, a3);
            #pragma unroll
            for (int np = 0; np < 4; np++) {
                const int n0 = np * 16;
                uint32_t b0, b1, b2, b3;
                ldsm4t(aW + ((kc + brow) * GSTR + n0 + bcol) * 2, b0, b1, b2, b3);
                mma16816(acc[np * 2], a0, a1, a2, a3, b0, b1);
                mma16816(acc[np * 2 + 1], a0, a1, a2, a3, b2, b3);
            }
        }
        __syncthreads();
    }

    const int r0 = bm + wid * 16 + (L >> 2);
    const int r1 = r0 + 8;
    #pragma unroll
    for (int j = 0; j < 8; j++) {
        const int col = bn + j * 8 + (L & 3) * 2;
        float v0 = acc[j][0] + bias[col], v1 = acc[j][1] + bias[col + 1];
        float v2 = acc[j][2] + bias[col], v3 = acc[j][3] + bias[col + 1];
        if (applyRope) {
            int j0 = (col & 63) >> 1;
            float c0 = g_cos[r0 * 32 + j0], s0 = g_sin[r0 * 32 + j0];
            float c1 = g_cos[r1 * 32 + j0], s1 = g_sin[r1 * 32 + j0];
            float t0 = v0 * c0 - v1 * s0, t1 = v0 * s0 + v1 * c0;
            float t2 = v2 * c1 - v3 * s1, t3 = v2 * s1 + v3 * c1;
            v0 = t0; v1 = t1; v2 = t2; v3 = t3;
        }
        if (Ch) {
            *(uint32_t*)&Ch[r0 * DM + col] = pack2(v0 * outScale, v1 * outScale);
            *(uint32_t*)&Ch[r1 * DM + col] = pack2(v2 * outScale, v3 * outScale);
        } else {
            *(float2*)&Cf[r0 * DM + col] = make_float2(v0, v1);
            *(float2*)&Cf[r1 * DM + col] = make_float2(v2, v3);
        }
    }
}

// merged QKV projection: grid (32, 4, 3)
__global__ void __launch_bounds__(256)
gemm_qkv_kernel(const float* __restrict__ bq, const float* __restrict__ bk,
                const float* __restrict__ bv) {
    const int z = blockIdx.z;
    const __half* A = (z == 0) ? g_qh : (z == 1) ? g_kh : g_vh;
    const __half* W = (z == 0) ? g_WQ : (z == 1) ? g_WK : g_WV;
    const float* bias = (z == 0) ? bq : (z == 1) ? bk : bv;
    __half* C = (z == 0) ? g_Qh : (z == 1) ? g_Kh : g_Vh;
    // Q scale folds log2e so softmax uses exp2: 0.125 * log2(e)
    const float sc = (z == 0) ? 0.18033688011112042f : 1.0f;
    gemm16_body(A, W, bias, nullptr, C, z < 2, sc);
}

// output projection: fp16 in, fp32 out
__global__ void __launch_bounds__(256)
gemm_out_kernel(const float* __restrict__ bo, float* __restrict__ out) {
    gemm16_body(g_Oh, g_WO, bo, out, nullptr, 0, 1.0f);
}

// ---------------- fp16 mma.sync flash attention, BM=128 ----------------------
// grid (32 q-tiles, 4 heads), 256 threads (8 warps). BM=128, BN=64, d=64.
// smem (dynamic): Q 128xKSTR @0 | K0 @18432 | K1 @27648 | V0 @36864 | V1 @46080
#define ATTN_SMEM 55296
__global__ void __launch_bounds__(256)
attn_kernel() {
    extern __shared__ __align__(16) char asmem[];
    const uint32_t base = smem_u32(asmem);
    const uint32_t qb = base;
    const uint32_t kB[2] = {base + 18432, base + 27648};
    const uint32_t vB[2] = {base + 36864, base + 46080};

    const int tid = threadIdx.x;
    const int wid = tid >> 5;
    const int L = tid & 31;
    const int h = blockIdx.y;
    const int q0 = blockIdx.x * 128;
    const int cb = h * HD;
    const int m0 = wid * 16;

    // ---- prologue: Q tile (128x64), then K0/V0 ----
    {
        #pragma unroll
        for (int t = 0; t < 4; t++) {
            int it = tid + t * 256;
            int row = it >> 3, ch = it & 7;
            cp16(qb + (row * KSTR + ch * 8) * 2, &g_Qh[(q0 + row) * DM + cb + ch * 8]);
        }
        CP_COMMIT();
        #pragma unroll
        for (int t = 0; t < 2; t++) {
            int it = tid + t * 256;
            int row = it >> 3, ch = it & 7;
            cp16(kB[0] + (row * KSTR + ch * 8) * 2, &g_Kh[row * DM + cb + ch * 8]);
        }
        #pragma unroll
        for (int t = 0; t < 2; t++) {
            int it = tid + t * 256;
            int row = it >> 3, ch = it & 7;
            cp16(vB[0] + (row * KSTR + ch * 8) * 2, &g_Vh[row * DM + cb + ch * 8]);
        }
        CP_COMMIT();
    }

    const uint32_t qaddr = qb + ((m0 + (L & 15)) * KSTR + (L >> 4) * 8) * 2;
    const int krow = (L >> 4) * 8 + (L & 7);
    const int kcol = ((L >> 3) & 1) * 8;
    const int vrow = ((L >> 3) & 1) * 8 + (L & 7);
    const int vcol = (L >> 4) * 8;

    // ones-column B fragment for row-sum MMA (col 0 only)
    const uint32_t onesB = (L < 4) ? 0x3C003C00u : 0u;

    float oa[8][4] = {};
    float lacc[4] = {};

    for (int i = 0; i < 64; i++) {
        const int buf = i & 1;
        if (i + 1 < 64) {
            const int nb = (i + 1) & 1;
            const int kt = (i + 1) * 64;
            #pragma unroll
            for (int t = 0; t < 2; t++) {
                int it = tid + t * 256;
                int row = it >> 3, ch = it & 7;
                cp16(kB[nb] + (row * KSTR + ch * 8) * 2, &g_Kh[(kt + row) * DM + cb + ch * 8]);
            }
            #pragma unroll
            for (int t = 0; t < 2; t++) {
                int it = tid + t * 256;
                int row = it >> 3, ch = it & 7;
                cp16(vB[nb] + (row * KSTR + ch * 8) * 2, &g_Vh[(kt + row) * DM + cb + ch * 8]);
            }
            CP_COMMIT();
            CP_WAIT(1);
        } else {
            CP_WAIT(0);
        }
        __syncthreads();

        const uint32_t kb = kB[buf];
        const uint32_t vb = vB[buf];

        // ---- S' = (Q*log2e/8) @ K^T : 16x64 per warp ----
        float sc[8][4] = {};
        #pragma unroll
        for (int kc4 = 0; kc4 < 4; kc4++) {
            const int kc = kc4 * 16;
            uint32_t a0, a1, a2, a3;
            ldsm4(qaddr + kc * 2, a0, a1, a2, a3);
            #pragma unroll
            for (int np = 0; np < 4; np++) {
                const int n0 = np * 16;
                uint32_t b0, b1, b2, b3;
                ldsm4(kb + ((n0 + krow) * KSTR + kc + kcol) * 2, b0, b1, b2, b3);
                mma16816(sc[np * 2], a0, a1, a2, a3, b0, b1);
                mma16816(sc[np * 2 + 1], a0, a1, a2, a3, b2, b3);
            }
        }

        // ---- P = 2^(S') packed f16x2 ----
        uint32_t pf[8][2];
        #pragma unroll
        for (int j = 0; j < 8; j++) {
            __half2 e0 = h2exp2(__floats2half2_rn(sc[j][0], sc[j][1]));
            __half2 e1 = h2exp2(__floats2half2_rn(sc[j][2], sc[j][3]));
            pf[j][0] = *(uint32_t*)&e0;
            pf[j][1] = *(uint32_t*)&e1;
        }

        // ---- O += P @ V ; l += P @ ones ----
        #pragma unroll
        for (int c = 0; c < 4; c++) {
            const int kc = c * 16;
            const uint32_t a0 = pf[2 * c][0], a1 = pf[2 * c][1];
            const uint32_t a2 = pf[2 * c + 1][0], a3 = pf[2 * c + 1][1];
            #pragma unroll
            for (int dp = 0; dp < 4; dp++) {
                const int n0 = dp * 16;
                uint32_t b0, b1, b2, b3;
                ldsm4t(vb + ((kc + vrow) * KSTR + n0 + vcol) * 2, b0, b1, b2, b3);
                mma16816(oa[dp * 2], a0, a1, a2, a3, b0, b1);
                mma16816(oa[dp * 2 + 1], a0, a1, a2, a3, b2, b3);
            }
            mma16816(lacc, a0, a1, a2, a3, onesB, onesB);
        }
        __syncthreads();
    }

    // ---- normalize + store fp16 ----
    const float l0 = __shfl_sync(0xffffffffu, lacc[0], L & 28);
    const float l1 = __shfl_sync(0xffffffffu, lacc[2], L & 28);
    const float inv0 = 1.0f / l0;
    const float inv1 = 1.0f / l1;
    const int r0 = q0 + m0 + (L >> 2);
    const int cc = (L & 3) * 2;
    #pragma unroll
    for (int j = 0; j < 8; j++) {
        *(uint32_t*)&g_Oh[r0 * DM + cb + j * 8 + cc] =
            pack2(oa[j][0] * inv0, oa[j][1] * inv0);
        *(uint32_t*)&g_Oh[(r0 + 8) * DM + cb + j * 8 + cc] =
            pack2(oa[j][2] * inv1, oa[j][3] * inv1);
    }
}

// ---------------- launch -----------------------------------------------------
extern "C" void kernel_launch(void* const* d_in, const int* in_sizes, int n_in,
                              void* d_out, int out_size) {
    const float* q  = (const float*)d_in[0];
    const float* k  = (const float*)d_in[1];
    const float* v  = (const float*)d_in[2];
    const float* wq = (const float*)d_in[3];
    const float* bq = (const float*)d_in[4];
    const float* wk = (const float*)d_in[5];
    const float* bk = (const float*)d_in[6];
    const float* wv = (const float*)d_in[7];
    const float* bv = (const float*)d_in[8];
    const float* wo = (const float*)d_in[9];
    const float* bo = (const float*)d_in[10];
    float* out = (float*)d_out;

    cudaFuncSetAttribute(gemm_qkv_kernel, cudaFuncAttributeMaxDynamicSharedMemorySize, GEMM_SMEM);
    cudaFuncSetAttribute(gemm_out_kernel, cudaFuncAttributeMaxDynamicSharedMemorySize, GEMM_SMEM);
    cudaFuncSetAttribute(attn_kernel, cudaFuncAttributeMaxDynamicSharedMemorySize, ATTN_SMEM);

    const int prepTot = 3 * (NTOK * DM / 4) + 4 * (DM * DM / 4) + NTOK * 32;
    prep_kernel<<<(prepTot + 255) / 256, 256>>>(q, k, v, wq, wk, wv, wo);

    gemm_qkv_kernel<<<dim3(NTOK / 128, DM / 64, 3), 256, GEMM_SMEM>>>(bq, bk, bv);

    attn_kernel<<<dim3(NTOK / 128, 4), 256, ATTN_SMEM>>>();

    gemm_out_kernel<<<dim3(NTOK / 128, DM / 64), 256, GEMM_SMEM>>>(bo, out);
}